// round 1
// baseline (speedup 1.0000x reference)
#include <cuda_runtime.h>

// DotProductAttention: out[s,b,h,:] = softmax_t(Q[s,b,h,:] . K[t,b,h,:]) @ V[t,b,h,:]
// Shapes: [2048, 2, 16, 64] fp32, NO score scaling (reference never applies norm_factor).
// Layout (all tensors + output): idx = s*2048 + b*1024 + h*64 + d.

#define SQc      2048
#define BHc      32          // B*NP = 2*16
#define RSTRIDE  2048        // row stride in elements (B*NP*HN)
#define HD       64
#define BM       64
#define BN       64
#define LDT      68          // padded stride for transposed K tile / P tile
#define NTH      256
#define LOG2E    1.4426950408889634f

#define SMEM_FLOATS (HD*64 + HD*LDT + BN*HD)   // Qt + (Kt|Ps) + Vs
#define SMEM_BYTES  (SMEM_FLOATS * 4)          // 50176 B

__global__ __launch_bounds__(NTH, 2)
void attn_flash_f32(const float* __restrict__ Q, const float* __restrict__ K,
                    const float* __restrict__ V, float* __restrict__ O) {
    extern __shared__ float smem[];
    float* Qt  = smem;                   // [HD][64]  : Qt[d][m]
    float* KtP = smem + HD * 64;         // [HD][LDT] : Kt[d][n]  -- aliased as Ps[m][LDT]
    float* Vs  = smem + HD * 64 + HD * LDT;  // [BN][HD] : Vs[n][d]

    const int tid = threadIdx.x;
    const int tx  = tid & 15;            // 16 columns of the thread grid
    const int ty  = tid >> 4;            // 16 rows
    const int bh  = blockIdx.y;
    const int bhoff = (bh >> 4) * 1024 + (bh & 15) * 64;
    const int qbase = blockIdx.x * BM;

    // ---- Load Q tile, transposed into Qt[d][m] ----
    #pragma unroll
    for (int it = 0; it < 4; it++) {
        int p  = tid + NTH * it;
        int r  = p >> 4;                  // query row within tile, 0..63
        int d0 = (p & 15) << 2;           // d offset, multiple of 4
        float4 v = *(const float4*)&Q[(size_t)(qbase + r) * RSTRIDE + bhoff + d0];
        Qt[(d0 + 0) * 64 + r] = v.x;
        Qt[(d0 + 1) * 64 + r] = v.y;
        Qt[(d0 + 2) * 64 + r] = v.z;
        Qt[(d0 + 3) * 64 + r] = v.w;
    }

    float mprev[4], lsum[4], acc_o[4][4];
    #pragma unroll
    for (int i = 0; i < 4; i++) {
        mprev[i] = -1e30f;
        lsum[i]  = 0.f;
        #pragma unroll
        for (int j = 0; j < 4; j++) acc_o[i][j] = 0.f;
    }

    for (int kt = 0; kt < SQc / BN; kt++) {
        __syncthreads();   // prior PV done reading KtP(=Ps) and Vs
        const int kbase = kt * BN;

        // ---- Load K tile transposed into Kt[d][n]; V tile direct into Vs[n][d] ----
        #pragma unroll
        for (int it = 0; it < 4; it++) {
            int p  = tid + NTH * it;
            int r  = p >> 4;
            int d0 = (p & 15) << 2;
            float4 kv = *(const float4*)&K[(size_t)(kbase + r) * RSTRIDE + bhoff + d0];
            KtP[(d0 + 0) * LDT + r] = kv.x;
            KtP[(d0 + 1) * LDT + r] = kv.y;
            KtP[(d0 + 2) * LDT + r] = kv.z;
            KtP[(d0 + 3) * LDT + r] = kv.w;
            float4 vv = *(const float4*)&V[(size_t)(kbase + r) * RSTRIDE + bhoff + d0];
            *(float4*)&Vs[r * HD + d0] = vv;
        }
        __syncthreads();

        // ---- S = Q . K^T  (4x4 per thread; rows m=4ty+i, cols n=4tx+j) ----
        float s[4][4];
        #pragma unroll
        for (int i = 0; i < 4; i++)
            #pragma unroll
            for (int j = 0; j < 4; j++) s[i][j] = 0.f;

        #pragma unroll 4
        for (int d = 0; d < HD; d++) {
            float4 q = *(const float4*)&Qt[d * 64 + 4 * ty];
            float4 k = *(const float4*)&KtP[d * LDT + 4 * tx];
            const float qa[4] = {q.x, q.y, q.z, q.w};
            const float ka[4] = {k.x, k.y, k.z, k.w};
            #pragma unroll
            for (int i = 0; i < 4; i++)
                #pragma unroll
                for (int j = 0; j < 4; j++)
                    s[i][j] = fmaf(qa[i], ka[j], s[i][j]);
        }

        // ---- Online softmax (base-2 domain); all 16 tx threads of a row group
        //      compute identical row stats via 16-lane shuffles ----
        float corr[4];
        #pragma unroll
        for (int i = 0; i < 4; i++) {
            float tmax = fmaxf(fmaxf(s[i][0], s[i][1]), fmaxf(s[i][2], s[i][3]));
            #pragma unroll
            for (int off = 8; off >= 1; off >>= 1)
                tmax = fmaxf(tmax, __shfl_xor_sync(0xffffffffu, tmax, off, 16));
            float mnew = fmaxf(mprev[i], tmax);
            corr[i] = exp2f((mprev[i] - mnew) * LOG2E);
            float rsum = 0.f;
            #pragma unroll
            for (int j = 0; j < 4; j++) {
                float pe = exp2f((s[i][j] - mnew) * LOG2E);
                s[i][j] = pe;
                rsum += pe;
            }
            #pragma unroll
            for (int off = 8; off >= 1; off >>= 1)
                rsum += __shfl_xor_sync(0xffffffffu, rsum, off, 16);
            lsum[i] = lsum[i] * corr[i] + rsum;
            mprev[i] = mnew;
            #pragma unroll
            for (int c = 0; c < 4; c++) acc_o[i][c] *= corr[i];
        }

        __syncthreads();   // all threads done reading Kt

        // ---- Write P into the aliased buffer: Ps[m][n], stride LDT ----
        #pragma unroll
        for (int i = 0; i < 4; i++) {
            float4 pr = make_float4(s[i][0], s[i][1], s[i][2], s[i][3]);
            *(float4*)&KtP[(4 * ty + i) * LDT + 4 * tx] = pr;
        }
        __syncthreads();

        // ---- O += P . V  (rows m=4ty+i, d-cols = 4tx+c) ----
        #pragma unroll 2
        for (int n0 = 0; n0 < BN; n0 += 4) {
            float4 pv[4], vv[4];
            #pragma unroll
            for (int i = 0; i < 4; i++)
                pv[i] = *(const float4*)&KtP[(4 * ty + i) * LDT + n0];
            #pragma unroll
            for (int j = 0; j < 4; j++)
                vv[j] = *(const float4*)&Vs[(n0 + j) * HD + 4 * tx];
            #pragma unroll
            for (int i = 0; i < 4; i++) {
                const float pa[4] = {pv[i].x, pv[i].y, pv[i].z, pv[i].w};
                #pragma unroll
                for (int j = 0; j < 4; j++) {
                    acc_o[i][0] = fmaf(pa[j], vv[j].x, acc_o[i][0]);
                    acc_o[i][1] = fmaf(pa[j], vv[j].y, acc_o[i][1]);
                    acc_o[i][2] = fmaf(pa[j], vv[j].z, acc_o[i][2]);
                    acc_o[i][3] = fmaf(pa[j], vv[j].w, acc_o[i][3]);
                }
            }
        }
    }

    // ---- Epilogue: normalize and store ----
    #pragma unroll
    for (int i = 0; i < 4; i++) {
        float inv = 1.f / lsum[i];
        float4 o = make_float4(acc_o[i][0] * inv, acc_o[i][1] * inv,
                               acc_o[i][2] * inv, acc_o[i][3] * inv);
        *(float4*)&O[(size_t)(qbase + 4 * ty + i) * RSTRIDE + bhoff + 4 * tx] = o;
    }
}

extern "C" void kernel_launch(void* const* d_in, const int* in_sizes, int n_in,
                              void* d_out, int out_size) {
    const float* Q = (const float*)d_in[0];
    const float* K = (const float*)d_in[1];
    const float* V = (const float*)d_in[2];
    float* O = (float*)d_out;

    cudaFuncSetAttribute(attn_flash_f32,
                         cudaFuncAttributeMaxDynamicSharedMemorySize, SMEM_BYTES);

    dim3 grid(SQc / BM, BHc);
    attn_flash_f32<<<grid, NTH, SMEM_BYTES>>>(Q, K, V, O);
}

// round 3
// speedup vs baseline: 3.1134x; 3.1134x over previous
#include <cuda_runtime.h>
#include <cuda_bf16.h>
#include <cstdint>

// DotProductAttention [2048,2,16,64] fp32, unscaled scores.
// mma.sync (HMMA) bf16 split-emulation flash attention.
// S = Qhi.Khi + Qhi.Klo + Qlo.Khi ; O = Phi.Vhi + Phi.Vlo + Plo.Vhi
#define SQc     2048
#define RSTRIDE 2048
#define BM      128
#define BN      64
#define NTH     256
#define NKT     (SQc / BN)
#define LOG2E   1.4426950408889634f
#define LDH     72                    // half-element row stride (144 B)

// smem byte offsets
#define S_QH  0                        // 128 x 72 halves = 18432 B
#define S_QL  18432
#define S_KH  36864                    // 64 x 72 halves = 9216 B
#define S_KL  46080
#define S_VH  55296
#define S_VL  64512
#define SMEM_TOTAL 73728

__device__ __forceinline__ uint32_t smem_u32(const void* p) {
    uint32_t a;
    asm("{ .reg .u64 t; cvta.to.shared.u64 t, %1; cvt.u32.u64 %0, t; }" : "=r"(a) : "l"(p));
    return a;
}
__device__ __forceinline__ float ex2(float x) {
    float r; asm("ex2.approx.ftz.f32 %0, %1;" : "=f"(r) : "f"(x)); return r;
}
// pack: result.hi16 = bf16(vhi), result.lo16 = bf16(vlo)
__device__ __forceinline__ uint32_t packbf2(float vhi, float vlo) {
    uint32_t r; asm("cvt.rn.bf16x2.f32 %0, %1, %2;" : "=r"(r) : "f"(vhi), "f"(vlo)); return r;
}
__device__ __forceinline__ float lo_f(uint32_t w) { return __uint_as_float(w << 16); }
__device__ __forceinline__ float hi_f(uint32_t w) { return __uint_as_float(w & 0xffff0000u); }

#define LDSM4(r0, r1, r2, r3, a) \
    asm volatile("ldmatrix.sync.aligned.m8n8.x4.shared.b16 {%0,%1,%2,%3}, [%4];" \
                 : "=r"(r0), "=r"(r1), "=r"(r2), "=r"(r3) : "r"(a))
#define LDSM4T(r0, r1, r2, r3, a) \
    asm volatile("ldmatrix.sync.aligned.m8n8.x4.trans.shared.b16 {%0,%1,%2,%3}, [%4];" \
                 : "=r"(r0), "=r"(r1), "=r"(r2), "=r"(r3) : "r"(a))
#define MMA16816(c, a, b0, b1) \
    asm volatile("mma.sync.aligned.m16n8k16.row.col.f32.bf16.bf16.f32 " \
                 "{%0,%1,%2,%3}, {%4,%5,%6,%7}, {%8,%9}, {%0,%1,%2,%3};" \
                 : "+f"((c)[0]), "+f"((c)[1]), "+f"((c)[2]), "+f"((c)[3]) \
                 : "r"((a)[0]), "r"((a)[1]), "r"((a)[2]), "r"((a)[3]), "r"(b0), "r"(b1))

// fp32 x8 -> bf16 hi x8 (16B) + lo residual x8 (16B)
__device__ __forceinline__ void cvt8_store(float4 a, float4 b, char* hp, char* lp) {
    uint32_t h0 = packbf2(a.y, a.x);
    uint32_t h1 = packbf2(a.w, a.z);
    uint32_t h2 = packbf2(b.y, b.x);
    uint32_t h3 = packbf2(b.w, b.z);
    uint32_t l0 = packbf2(a.y - hi_f(h0), a.x - lo_f(h0));
    uint32_t l1 = packbf2(a.w - hi_f(h1), a.z - lo_f(h1));
    uint32_t l2 = packbf2(b.y - hi_f(h2), b.x - lo_f(h2));
    uint32_t l3 = packbf2(b.w - hi_f(h3), b.z - lo_f(h3));
    *(uint4*)hp = make_uint4(h0, h1, h2, h3);
    *(uint4*)lp = make_uint4(l0, l1, l2, l3);
}

__global__ __launch_bounds__(NTH, 1)
void attn_hmma(const float* __restrict__ Q, const float* __restrict__ K,
               const float* __restrict__ V, float* __restrict__ Og) {
    extern __shared__ char smc[];
    const uint32_t sb = smem_u32(smc);
    const int tid = threadIdx.x;
    const int wid = tid >> 5;
    const int lane = tid & 31;
    const int g  = lane >> 2;         // quad row
    const int tg = lane & 3;          // quad col
    const int warp_m = wid * 16;
    const int bh = blockIdx.y;
    const int bhoff = (bh >> 4) * 1024 + (bh & 15) * 64;
    const int qbase = blockIdx.x * BM;

    // ---- Q tile fp32 -> bf16 hi/lo into smem ----
    #pragma unroll
    for (int i = 0; i < 4; i++) {
        int c = tid + NTH * i;                // 1024 chunks of 8 elems
        int row = c >> 3, d0 = (c & 7) * 8;
        const float* gq = Q + (size_t)(qbase + row) * RSTRIDE + bhoff + d0;
        float4 a = *(const float4*)gq;
        float4 b = *(const float4*)(gq + 4);
        int off = (row * LDH + d0) * 2;
        cvt8_store(a, b, smc + S_QH + off, smc + S_QL + off);
    }

    // ---- per-lane ldmatrix base addresses ----
    const int lb8  = (lane >> 3) & 1;
    const int lb16 = (lane >> 4) & 1;
    // Q A-frag: row = warp_m + (lane&15), col = 16*kk + 8*lb16
    const uint32_t aQbase = sb + ((warp_m + (lane & 15)) * LDH + 8 * lb16) * 2;
    // K B-frag: key = 16*j2 + 8*lb16 + (lane&7), col = 16*kk + 8*lb8
    const uint32_t bKbase = sb + ((8 * lb16 + (lane & 7)) * LDH + 8 * lb8) * 2;
    // V B-frag (trans): key = 16*kk + 8*lb8 + (lane&7), col(d) = 16*j2 + 8*lb16
    const uint32_t bVbase = sb + ((8 * lb8 + (lane & 7)) * LDH + 8 * lb16) * 2;

    float o[8][4];
    #pragma unroll
    for (int j = 0; j < 8; j++)
        #pragma unroll
        for (int c = 0; c < 4; c++) o[j][c] = 0.f;
    float m0 = -1e30f, m1 = -1e30f, l0 = 0.f, l1 = 0.f;

    __syncthreads();   // Q smem visible

    // ---- load Q A-fragments once (hi + lo), keep in registers ----
    uint32_t aQH[4][4], aQL[4][4];
    #pragma unroll
    for (int kk = 0; kk < 4; kk++) {
        LDSM4(aQH[kk][0], aQH[kk][1], aQH[kk][2], aQH[kk][3], aQbase + S_QH + kk * 32);
        LDSM4(aQL[kk][0], aQL[kk][1], aQL[kk][2], aQL[kk][3], aQbase + S_QL + kk * 32);
    }

    for (int kt = 0; kt < NKT; kt++) {
        const int kbase = kt * BN;
        __syncthreads();   // previous iter done reading K/V smem

        // ---- K/V tiles fp32 -> bf16 hi/lo ----
        #pragma unroll
        for (int i = 0; i < 2; i++) {
            int c = tid + NTH * i;             // 512 chunks
            int row = c >> 3, d0 = (c & 7) * 8;
            int off = (row * LDH + d0) * 2;
            const float* gk = K + (size_t)(kbase + row) * RSTRIDE + bhoff + d0;
            float4 a = *(const float4*)gk;
            float4 b = *(const float4*)(gk + 4);
            cvt8_store(a, b, smc + S_KH + off, smc + S_KL + off);
            const float* gv = V + (size_t)(kbase + row) * RSTRIDE + bhoff + d0;
            float4 av = *(const float4*)gv;
            float4 bv = *(const float4*)(gv + 4);
            cvt8_store(av, bv, smc + S_VH + off, smc + S_VL + off);
        }
        __syncthreads();

        // ---- GEMM1: S = Qhi.KhiT + Qlo.KhiT + Qhi.KloT ----
        float s[8][4];
        #pragma unroll
        for (int j = 0; j < 8; j++)
            #pragma unroll
            for (int c = 0; c < 4; c++) s[j][c] = 0.f;

        #pragma unroll
        for (int kk = 0; kk < 4; kk++) {
            #pragma unroll
            for (int j2 = 0; j2 < 4; j2++) {
                uint32_t b0, b1, b2, b3;
                LDSM4(b0, b1, b2, b3, bKbase + S_KH + j2 * (16 * LDH * 2) + kk * 32);
                MMA16816(s[2 * j2],     aQH[kk], b0, b1);
                MMA16816(s[2 * j2 + 1], aQH[kk], b2, b3);
                MMA16816(s[2 * j2],     aQL[kk], b0, b1);
                MMA16816(s[2 * j2 + 1], aQL[kk], b2, b3);
            }
            #pragma unroll
            for (int j2 = 0; j2 < 4; j2++) {
                uint32_t b0, b1, b2, b3;
                LDSM4(b0, b1, b2, b3, bKbase + S_KL + j2 * (16 * LDH * 2) + kk * 32);
                MMA16816(s[2 * j2],     aQH[kk], b0, b1);
                MMA16816(s[2 * j2 + 1], aQH[kk], b2, b3);
            }
        }

        // ---- online softmax (warp-local; rows g and g+8) ----
        float mx0 = -1e30f, mx1 = -1e30f;
        #pragma unroll
        for (int j = 0; j < 8; j++) {
            mx0 = fmaxf(mx0, fmaxf(s[j][0], s[j][1]));
            mx1 = fmaxf(mx1, fmaxf(s[j][2], s[j][3]));
        }
        mx0 = fmaxf(mx0, __shfl_xor_sync(0xffffffffu, mx0, 1));
        mx0 = fmaxf(mx0, __shfl_xor_sync(0xffffffffu, mx0, 2));
        mx1 = fmaxf(mx1, __shfl_xor_sync(0xffffffffu, mx1, 1));
        mx1 = fmaxf(mx1, __shfl_xor_sync(0xffffffffu, mx1, 2));
        float mn0 = fmaxf(m0, mx0), mn1 = fmaxf(m1, mx1);
        float corr0 = ex2((m0 - mn0) * LOG2E);
        float corr1 = ex2((m1 - mn1) * LOG2E);
        m0 = mn0; m1 = mn1;
        float nb0 = mn0 * LOG2E, nb1 = mn1 * LOG2E;
        float rs0 = 0.f, rs1 = 0.f;
        #pragma unroll
        for (int j = 0; j < 8; j++) {
            s[j][0] = ex2(fmaf(s[j][0], LOG2E, -nb0));
            s[j][1] = ex2(fmaf(s[j][1], LOG2E, -nb0));
            s[j][2] = ex2(fmaf(s[j][2], LOG2E, -nb1));
            s[j][3] = ex2(fmaf(s[j][3], LOG2E, -nb1));
            rs0 += s[j][0] + s[j][1];
            rs1 += s[j][2] + s[j][3];
        }
        rs0 += __shfl_xor_sync(0xffffffffu, rs0, 1);
        rs0 += __shfl_xor_sync(0xffffffffu, rs0, 2);
        rs1 += __shfl_xor_sync(0xffffffffu, rs1, 1);
        rs1 += __shfl_xor_sync(0xffffffffu, rs1, 2);
        l0 = l0 * corr0 + rs0;
        l1 = l1 * corr1 + rs1;

        // ---- P -> A-fragments (hi + lo residual), in registers ----
        uint32_t aPH[4][4], aPL[4][4];
        #pragma unroll
        for (int kk = 0; kk < 4; kk++) {
            int j = 2 * kk, j1 = 2 * kk + 1;
            uint32_t h;
            h = packbf2(s[j][1], s[j][0]);  aPH[kk][0] = h;
            aPL[kk][0] = packbf2(s[j][1] - hi_f(h), s[j][0] - lo_f(h));
            h = packbf2(s[j][3], s[j][2]);  aPH[kk][1] = h;
            aPL[kk][1] = packbf2(s[j][3] - hi_f(h), s[j][2] - lo_f(h));
            h = packbf2(s[j1][1], s[j1][0]); aPH[kk][2] = h;
            aPL[kk][2] = packbf2(s[j1][1] - hi_f(h), s[j1][0] - lo_f(h));
            h = packbf2(s[j1][3], s[j1][2]); aPH[kk][3] = h;
            aPL[kk][3] = packbf2(s[j1][3] - hi_f(h), s[j1][2] - lo_f(h));
        }

        // ---- rescale O ----
        #pragma unroll
        for (int j = 0; j < 8; j++) {
            o[j][0] *= corr0; o[j][1] *= corr0;
            o[j][2] *= corr1; o[j][3] *= corr1;
        }

        // ---- GEMM2: O += Phi.Vhi + Plo.Vhi + Phi.Vlo ----
        #pragma unroll
        for (int kk = 0; kk < 4; kk++) {
            #pragma unroll
            for (int j2 = 0; j2 < 4; j2++) {
                uint32_t b0, b1, b2, b3;
                LDSM4T(b0, b1, b2, b3, bVbase + S_VH + kk * (16 * LDH * 2) + j2 * 32);
                MMA16816(o[2 * j2],     aPH[kk], b0, b1);
                MMA16816(o[2 * j2 + 1], aPH[kk], b2, b3);
                MMA16816(o[2 * j2],     aPL[kk], b0, b1);
                MMA16816(o[2 * j2 + 1], aPL[kk], b2, b3);
            }
            #pragma unroll
            for (int j2 = 0; j2 < 4; j2++) {
                uint32_t b0, b1, b2, b3;
                LDSM4T(b0, b1, b2, b3, bVbase + S_VL + kk * (16 * LDH * 2) + j2 * 32);
                MMA16816(o[2 * j2],     aPH[kk], b0, b1);
                MMA16816(o[2 * j2 + 1], aPH[kk], b2, b3);
            }
        }
    }

    // ---- epilogue ----
    float inv0 = 1.f / l0, inv1 = 1.f / l1;
    const int row0 = qbase + warp_m + g;
    float* d0p = Og + (size_t)row0 * RSTRIDE + bhoff + 2 * tg;
    float* d1p = d0p + 8 * RSTRIDE;
    #pragma unroll
    for (int j = 0; j < 8; j++) {
        *(float2*)(d0p + 8 * j) = make_float2(o[j][0] * inv0, o[j][1] * inv0);
        *(float2*)(d1p + 8 * j) = make_float2(o[j][2] * inv1, o[j][3] * inv1);
    }
}

extern "C" void kernel_launch(void* const* d_in, const int* in_sizes, int n_in,
                              void* d_out, int out_size) {
    const float* Q = (const float*)d_in[0];
    const float* K = (const float*)d_in[1];
    const float* V = (const float*)d_in[2];
    float* O = (float*)d_out;

    cudaFuncSetAttribute(attn_hmma, cudaFuncAttributeMaxDynamicSharedMemorySize, SMEM_TOTAL);
    dim3 grid(SQc / BM, 32);
    attn_hmma<<<grid, NTH, SMEM_TOTAL>>>(Q, K, V, O);
}

// round 4
// speedup vs baseline: 3.4711x; 1.1149x over previous
#include <cuda_runtime.h>
#include <cuda_bf16.h>
#include <cstdint>

// DotProductAttention [2048,2,16,64] fp32, unscaled scores.
// mma.sync (HMMA) bf16 split-emulation flash attention, double-buffered K/V.
// S = Qhi.Khi + Qhi.Klo + Qlo.Khi ; O = Phi.Vhi + Phi.Vlo + Plo.Vhi
#define SQc     2048
#define RSTRIDE 2048
#define BM      128
#define BN      64
#define NTH     256
#define NKT     (SQc / BN)
#define LOG2E   1.4426950408889634f
#define LDH     72                    // half-element row stride (144 B)

// smem byte offsets
#define S_QH   0                       // 128 x 72 halves = 18432 B
#define S_QL   18432
#define S_KV0  36864                   // two K/V buffers, 36864 B each
#define KVBUF  36864
#define KH_REL 0                       // 64 x 72 halves = 9216 B each
#define KL_REL 9216
#define VH_REL 18432
#define VL_REL 27648
#define SMEM_TOTAL (36864 + 2 * 36864)   // 110592 B

__device__ __forceinline__ uint32_t smem_u32(const void* p) {
    uint32_t a;
    asm("{ .reg .u64 t; cvta.to.shared.u64 t, %1; cvt.u32.u64 %0, t; }" : "=r"(a) : "l"(p));
    return a;
}
__device__ __forceinline__ float ex2(float x) {
    float r; asm("ex2.approx.ftz.f32 %0, %1;" : "=f"(r) : "f"(x)); return r;
}
// pack: result.hi16 = bf16(vhi), result.lo16 = bf16(vlo)
__device__ __forceinline__ uint32_t packbf2(float vhi, float vlo) {
    uint32_t r; asm("cvt.rn.bf16x2.f32 %0, %1, %2;" : "=r"(r) : "f"(vhi), "f"(vlo)); return r;
}
__device__ __forceinline__ float lo_f(uint32_t w) { return __uint_as_float(w << 16); }
__device__ __forceinline__ float hi_f(uint32_t w) { return __uint_as_float(w & 0xffff0000u); }

#define LDSM4(r0, r1, r2, r3, a) \
    asm volatile("ldmatrix.sync.aligned.m8n8.x4.shared.b16 {%0,%1,%2,%3}, [%4];" \
                 : "=r"(r0), "=r"(r1), "=r"(r2), "=r"(r3) : "r"(a))
#define LDSM4T(r0, r1, r2, r3, a) \
    asm volatile("ldmatrix.sync.aligned.m8n8.x4.trans.shared.b16 {%0,%1,%2,%3}, [%4];" \
                 : "=r"(r0), "=r"(r1), "=r"(r2), "=r"(r3) : "r"(a))
#define MMA16816(c, a, b0, b1) \
    asm volatile("mma.sync.aligned.m16n8k16.row.col.f32.bf16.bf16.f32 " \
                 "{%0,%1,%2,%3}, {%4,%5,%6,%7}, {%8,%9}, {%0,%1,%2,%3};" \
                 : "+f"((c)[0]), "+f"((c)[1]), "+f"((c)[2]), "+f"((c)[3]) \
                 : "r"((a)[0]), "r"((a)[1]), "r"((a)[2]), "r"((a)[3]), "r"(b0), "r"(b1))

// fp32 x8 -> bf16 hi x8 (16B) + lo residual x8 (16B)
__device__ __forceinline__ void cvt8_store(float4 a, float4 b, char* hp, char* lp) {
    uint32_t h0 = packbf2(a.y, a.x);
    uint32_t h1 = packbf2(a.w, a.z);
    uint32_t h2 = packbf2(b.y, b.x);
    uint32_t h3 = packbf2(b.w, b.z);
    uint32_t l0 = packbf2(a.y - hi_f(h0), a.x - lo_f(h0));
    uint32_t l1 = packbf2(a.w - hi_f(h1), a.z - lo_f(h1));
    uint32_t l2 = packbf2(b.y - hi_f(h2), b.x - lo_f(h2));
    uint32_t l3 = packbf2(b.w - hi_f(h3), b.z - lo_f(h3));
    *(uint4*)hp = make_uint4(h0, h1, h2, h3);
    *(uint4*)lp = make_uint4(l0, l1, l2, l3);
}

__global__ __launch_bounds__(NTH, 1)
void attn_hmma(const float* __restrict__ Q, const float* __restrict__ K,
               const float* __restrict__ V, float* __restrict__ Og) {
    extern __shared__ char smc[];
    const uint32_t sb = smem_u32(smc);
    const int tid = threadIdx.x;
    const int wid = tid >> 5;
    const int lane = tid & 31;
    const int g  = lane >> 2;         // quad row
    const int tg = lane & 3;          // quad col
    const int warp_m = wid * 16;
    const int bh = blockIdx.y;
    const int bhoff = (bh >> 4) * 1024 + (bh & 15) * 64;
    const int qbase = blockIdx.x * BM;

    // ---- per-thread K/V chunk geometry (2 chunks of 8 elems per thread) ----
    // chunk c = tid + 256*i : row = c>>3 (0..63), d0 = (c&7)*8
    const int row0 = tid >> 3,        d00 = (tid & 7) * 8;
    const int row1 = (tid + NTH) >> 3, d01 = ((tid + NTH) & 7) * 8;
    const int soff0 = (row0 * LDH + d00) * 2;
    const int soff1 = (row1 * LDH + d01) * 2;
    const size_t goff0 = (size_t)row0 * RSTRIDE + bhoff + d00;
    const size_t goff1 = (size_t)row1 * RSTRIDE + bhoff + d01;

    // ---- Q tile fp32 -> bf16 hi/lo into smem ----
    #pragma unroll
    for (int i = 0; i < 4; i++) {
        int c = tid + NTH * i;                // 1024 chunks of 8 elems
        int row = c >> 3, d0 = (c & 7) * 8;
        const float* gq = Q + (size_t)(qbase + row) * RSTRIDE + bhoff + d0;
        float4 a = *(const float4*)gq;
        float4 b = *(const float4*)(gq + 4);
        int off = (row * LDH + d0) * 2;
        cvt8_store(a, b, smc + S_QH + off, smc + S_QL + off);
    }

    // ---- prefetch K/V tile 0 and store into buffer 0 ----
    float4 pk0a, pk0b, pk1a, pk1b, pv0a, pv0b, pv1a, pv1b;
    {
        const float* gk0 = K + goff0;
        const float* gk1 = K + goff1;
        const float* gv0 = V + goff0;
        const float* gv1 = V + goff1;
        pk0a = *(const float4*)gk0; pk0b = *(const float4*)(gk0 + 4);
        pk1a = *(const float4*)gk1; pk1b = *(const float4*)(gk1 + 4);
        pv0a = *(const float4*)gv0; pv0b = *(const float4*)(gv0 + 4);
        pv1a = *(const float4*)gv1; pv1b = *(const float4*)(gv1 + 4);
        char* b0 = smc + S_KV0;
        cvt8_store(pk0a, pk0b, b0 + KH_REL + soff0, b0 + KL_REL + soff0);
        cvt8_store(pk1a, pk1b, b0 + KH_REL + soff1, b0 + KL_REL + soff1);
        cvt8_store(pv0a, pv0b, b0 + VH_REL + soff0, b0 + VL_REL + soff0);
        cvt8_store(pv1a, pv1b, b0 + VH_REL + soff1, b0 + VL_REL + soff1);
    }

    // ---- per-lane ldmatrix offsets ----
    const int lb8  = (lane >> 3) & 1;
    const int lb16 = (lane >> 4) & 1;
    // Q A-frag: row = warp_m + (lane&15), col = 16*kk + 8*lb16
    const uint32_t aQbase = sb + ((warp_m + (lane & 15)) * LDH + 8 * lb16) * 2;
    // K B-frag (in-buffer offset): key = 16*j2 + 8*lb16 + (lane&7), col = 16*kk + 8*lb8
    const uint32_t bKoff = ((8 * lb16 + (lane & 7)) * LDH + 8 * lb8) * 2;
    // V B-frag (trans, in-buffer): key = 16*kk + 8*lb8 + (lane&7), col(d) = 16*j2 + 8*lb16
    const uint32_t bVoff = ((8 * lb8 + (lane & 7)) * LDH + 8 * lb16) * 2;

    float o[8][4];
    #pragma unroll
    for (int j = 0; j < 8; j++)
        #pragma unroll
        for (int c = 0; c < 4; c++) o[j][c] = 0.f;
    float m0 = -1e30f, m1 = -1e30f, l0 = 0.f, l1 = 0.f;

    __syncthreads();   // Q smem + K/V buffer 0 visible

    // ---- load Q A-fragments once (hi + lo), keep in registers ----
    uint32_t aQH[4][4], aQL[4][4];
    #pragma unroll
    for (int kk = 0; kk < 4; kk++) {
        LDSM4(aQH[kk][0], aQH[kk][1], aQH[kk][2], aQH[kk][3], aQbase + S_QH + kk * 32);
        LDSM4(aQL[kk][0], aQL[kk][1], aQL[kk][2], aQL[kk][3], aQbase + S_QL + kk * 32);
    }

    for (int kt = 0; kt < NKT; kt++) {
        const uint32_t cur = sb + S_KV0 + (uint32_t)(kt & 1) * KVBUF;
        const uint32_t bK = cur + bKoff;
        const uint32_t bV = cur + bVoff;

        // ---- GEMM1: S = Qhi.KhiT + Qlo.KhiT + Qhi.KloT ----
        float s[8][4];
        #pragma unroll
        for (int j = 0; j < 8; j++)
            #pragma unroll
            for (int c = 0; c < 4; c++) s[j][c] = 0.f;

        #pragma unroll
        for (int kk = 0; kk < 4; kk++) {
            #pragma unroll
            for (int j2 = 0; j2 < 4; j2++) {
                uint32_t b0, b1, b2, b3;
                LDSM4(b0, b1, b2, b3, bK + KH_REL + j2 * (16 * LDH * 2) + kk * 32);
                MMA16816(s[2 * j2],     aQH[kk], b0, b1);
                MMA16816(s[2 * j2 + 1], aQH[kk], b2, b3);
                MMA16816(s[2 * j2],     aQL[kk], b0, b1);
                MMA16816(s[2 * j2 + 1], aQL[kk], b2, b3);
            }
            #pragma unroll
            for (int j2 = 0; j2 < 4; j2++) {
                uint32_t b0, b1, b2, b3;
                LDSM4(b0, b1, b2, b3, bK + KL_REL + j2 * (16 * LDH * 2) + kk * 32);
                MMA16816(s[2 * j2],     aQH[kk], b0, b1);
                MMA16816(s[2 * j2 + 1], aQH[kk], b2, b3);
            }
        }

        // ---- issue next tile's global loads (latency hidden by softmax+GEMM2) ----
        const bool haveNext = (kt + 1 < NKT);
        if (haveNext) {
            const size_t kb = (size_t)(kt + 1) * BN * RSTRIDE;
            const float* gk0 = K + kb + goff0;
            const float* gk1 = K + kb + goff1;
            const float* gv0 = V + kb + goff0;
            const float* gv1 = V + kb + goff1;
            pk0a = *(const float4*)gk0; pk0b = *(const float4*)(gk0 + 4);
            pk1a = *(const float4*)gk1; pk1b = *(const float4*)(gk1 + 4);
            pv0a = *(const float4*)gv0; pv0b = *(const float4*)(gv0 + 4);
            pv1a = *(const float4*)gv1; pv1b = *(const float4*)(gv1 + 4);
        }

        // ---- online softmax (warp-local; rows g and g+8) ----
        float mx0 = -1e30f, mx1 = -1e30f;
        #pragma unroll
        for (int j = 0; j < 8; j++) {
            mx0 = fmaxf(mx0, fmaxf(s[j][0], s[j][1]));
            mx1 = fmaxf(mx1, fmaxf(s[j][2], s[j][3]));
        }
        mx0 = fmaxf(mx0, __shfl_xor_sync(0xffffffffu, mx0, 1));
        mx0 = fmaxf(mx0, __shfl_xor_sync(0xffffffffu, mx0, 2));
        mx1 = fmaxf(mx1, __shfl_xor_sync(0xffffffffu, mx1, 1));
        mx1 = fmaxf(mx1, __shfl_xor_sync(0xffffffffu, mx1, 2));
        float mn0 = fmaxf(m0, mx0), mn1 = fmaxf(m1, mx1);
        float corr0 = ex2((m0 - mn0) * LOG2E);
        float corr1 = ex2((m1 - mn1) * LOG2E);
        m0 = mn0; m1 = mn1;
        float nb0 = mn0 * LOG2E, nb1 = mn1 * LOG2E;
        float rs0 = 0.f, rs1 = 0.f;
        #pragma unroll
        for (int j = 0; j < 8; j++) {
            s[j][0] = ex2(fmaf(s[j][0], LOG2E, -nb0));
            s[j][1] = ex2(fmaf(s[j][1], LOG2E, -nb0));
            s[j][2] = ex2(fmaf(s[j][2], LOG2E, -nb1));
            s[j][3] = ex2(fmaf(s[j][3], LOG2E, -nb1));
            rs0 += s[j][0] + s[j][1];
            rs1 += s[j][2] + s[j][3];
        }
        rs0 += __shfl_xor_sync(0xffffffffu, rs0, 1);
        rs0 += __shfl_xor_sync(0xffffffffu, rs0, 2);
        rs1 += __shfl_xor_sync(0xffffffffu, rs1, 1);
        rs1 += __shfl_xor_sync(0xffffffffu, rs1, 2);
        l0 = l0 * corr0 + rs0;
        l1 = l1 * corr1 + rs1;

        // ---- P -> A-fragments (hi + lo residual), in registers ----
        uint32_t aPH[4][4], aPL[4][4];
        #pragma unroll
        for (int kk = 0; kk < 4; kk++) {
            int j = 2 * kk, j1 = 2 * kk + 1;
            uint32_t h;
            h = packbf2(s[j][1], s[j][0]);  aPH[kk][0] = h;
            aPL[kk][0] = packbf2(s[j][1] - hi_f(h), s[j][0] - lo_f(h));
            h = packbf2(s[j][3], s[j][2]);  aPH[kk][1] = h;
            aPL[kk][1] = packbf2(s[j][3] - hi_f(h), s[j][2] - lo_f(h));
            h = packbf2(s[j1][1], s[j1][0]); aPH[kk][2] = h;
            aPL[kk][2] = packbf2(s[j1][1] - hi_f(h), s[j1][0] - lo_f(h));
            h = packbf2(s[j1][3], s[j1][2]); aPH[kk][3] = h;
            aPL[kk][3] = packbf2(s[j1][3] - hi_f(h), s[j1][2] - lo_f(h));
        }

        // ---- rescale O ----
        #pragma unroll
        for (int j = 0; j < 8; j++) {
            o[j][0] *= corr0; o[j][1] *= corr0;
            o[j][2] *= corr1; o[j][3] *= corr1;
        }

        // ---- GEMM2: O += Phi.Vhi + Plo.Vhi + Phi.Vlo ----
        #pragma unroll
        for (int kk = 0; kk < 4; kk++) {
            #pragma unroll
            for (int j2 = 0; j2 < 4; j2++) {
                uint32_t b0, b1, b2, b3;
                LDSM4T(b0, b1, b2, b3, bV + VH_REL + kk * (16 * LDH * 2) + j2 * 32);
                MMA16816(o[2 * j2],     aPH[kk], b0, b1);
                MMA16816(o[2 * j2 + 1], aPH[kk], b2, b3);
                MMA16816(o[2 * j2],     aPL[kk], b0, b1);
                MMA16816(o[2 * j2 + 1], aPL[kk], b2, b3);
            }
            #pragma unroll
            for (int j2 = 0; j2 < 4; j2++) {
                uint32_t b0, b1, b2, b3;
                LDSM4T(b0, b1, b2, b3, bV + VL_REL + kk * (16 * LDH * 2) + j2 * 32);
                MMA16816(o[2 * j2],     aPH[kk], b0, b1);
                MMA16816(o[2 * j2 + 1], aPH[kk], b2, b3);
            }
        }

        // ---- store next tile into the other buffer, then one barrier ----
        if (haveNext) {
            char* nx = smc + S_KV0 + ((kt + 1) & 1) * KVBUF;
            cvt8_store(pk0a, pk0b, nx + KH_REL + soff0, nx + KL_REL + soff0);
            cvt8_store(pk1a, pk1b, nx + KH_REL + soff1, nx + KL_REL + soff1);
            cvt8_store(pv0a, pv0b, nx + VH_REL + soff0, nx + VL_REL + soff0);
            cvt8_store(pv1a, pv1b, nx + VH_REL + soff1, nx + VL_REL + soff1);
            __syncthreads();
        }
    }

    // ---- epilogue ----
    float inv0 = 1.f / l0, inv1 = 1.f / l1;
    const int orow = qbase + warp_m + g;
    float* d0p = Og + (size_t)orow * RSTRIDE + bhoff + 2 * tg;
    float* d1p = d0p + 8 * RSTRIDE;
    #pragma unroll
    for (int j = 0; j < 8; j++) {
        *(float2*)(d0p + 8 * j) = make_float2(o[j][0] * inv0, o[j][1] * inv0);
        *(float2*)(d1p + 8 * j) = make_float2(o[j][2] * inv1, o[j][3] * inv1);
    }
}

extern "C" void kernel_launch(void* const* d_in, const int* in_sizes, int n_in,
                              void* d_out, int out_size) {
    const float* Q = (const float*)d_in[0];
    const float* K = (const float*)d_in[1];
    const float* V = (const float*)d_in[2];
    float* O = (float*)d_out;

    cudaFuncSetAttribute(attn_hmma, cudaFuncAttributeMaxDynamicSharedMemorySize, SMEM_TOTAL);
    dim3 grid(SQc / BM, 32);
    attn_hmma<<<grid, NTH, SMEM_TOTAL>>>(Q, K, V, O);
}